// round 12
// baseline (speedup 1.0000x reference)
#include <cuda_runtime.h>
#include <cuda_fp16.h>
#include <cstdint>

#define Bb 512
#define Tt 256
#define Hh 1024
#define NCTA 128
#define KCH 64
#define NCHUNK 16          // 1024 / 64
#define NSTG 4
#define STAGE_BYTES 24576  // A tile 8KB + B tile 16KB
#define GRP_BYTES (NSTG * STAGE_BYTES)   // 98304 per group
#define NTHREADS 512
#define SMEM_DYN (2048 + 2 * GRP_BYTES + 1024)

// persistent device state (static allocation — no cudaMalloc)
__device__ __half g_h[2 * Bb * Hh];        // DOUBLE-BUFFERED hidden state, fp16
__device__ __half g_wp[32 * 128 * Hh];     // packed W_hh slabs, fp16 (gate-interleaved)
__device__ float  g_xT[Tt * Bb];           // x transposed [T,B]
__device__ int    g_f[4 * 2 * 32];         // [mb][half][jb] = steps published

// ---------------- helpers ----------------
__device__ __forceinline__ uint32_t smem_u32(const void* p) {
    uint32_t a;
    asm("{ .reg .u64 t; cvta.to.shared.u64 t, %1; cvt.u32.u64 %0, t; }" : "=r"(a) : "l"(p));
    return a;
}
__device__ __forceinline__ void cp16(uint32_t dst, const void* src) {
    unsigned long long g = __cvta_generic_to_global(src);
    asm volatile("cp.async.cg.shared.global [%0], [%1], 16;" :: "r"(dst), "l"(g) : "memory");
}
__device__ __forceinline__ void cp_commit() {
    asm volatile("cp.async.commit_group;" ::: "memory");
}
__device__ __forceinline__ void cp_wait2() {
    asm volatile("cp.async.wait_group 2;" ::: "memory");
}
__device__ __forceinline__ void cp_wait0() {
    asm volatile("cp.async.wait_group 0;" ::: "memory");
}
__device__ __forceinline__ void bar_named(int id) {
    asm volatile("bar.sync %0, 256;" :: "r"(id) : "memory");
}
__device__ __forceinline__ void ldsm_x4(uint32_t (&r)[4], uint32_t addr) {
    asm volatile("ldmatrix.sync.aligned.m8n8.x4.shared.b16 {%0,%1,%2,%3}, [%4];"
        : "=r"(r[0]), "=r"(r[1]), "=r"(r[2]), "=r"(r[3]) : "r"(addr));
}
__device__ __forceinline__ void mma16816(float (&d)[4], const uint32_t (&a)[4],
                                         uint32_t b0, uint32_t b1) {
    asm volatile("mma.sync.aligned.m16n8k16.row.col.f32.f16.f16.f32 "
        "{%0,%1,%2,%3}, {%4,%5,%6,%7}, {%8,%9}, {%0,%1,%2,%3};"
        : "+f"(d[0]), "+f"(d[1]), "+f"(d[2]), "+f"(d[3])
        : "r"(a[0]), "r"(a[1]), "r"(a[2]), "r"(a[3]), "r"(b0), "r"(b1));
}
__device__ __forceinline__ float sigm(float x) { return 1.0f / (1.0f + __expf(-x)); }
__device__ __forceinline__ float tanh_(float x) { return 2.0f / (1.0f + __expf(-2.0f * x)) - 1.0f; }

// acquire-load a pair of adjacent flags (producers 2cc, 2cc+1)
__device__ __forceinline__ uint64_t ld_flags(const int* p) {
    uint32_t lo, hi;
    asm volatile("ld.acquire.gpu.global.v2.u32 {%0,%1}, [%2];"
        : "=r"(lo), "=r"(hi) : "l"(p) : "memory");
    return ((uint64_t)hi << 32) | lo;
}
__device__ __forceinline__ bool flags_ok(uint64_t v, int t) {
    return ((int)(v & 0xffffffffu) >= t) && ((int)(v >> 32) >= t);
}
__device__ __forceinline__ void st_flag_release(int* p, int v) {
    asm volatile("st.release.gpu.global.b32 [%0], %1;" :: "l"(p), "r"(v) : "memory");
}

// swizzled byte offset within a 128B-row tile (granule = 16B, 8 per row)
__device__ __forceinline__ uint32_t swz(int r, int g) {
    return (uint32_t)(r * 128) + (uint32_t)(((g ^ (r & 7)) & 7) << 4);
}

// ---------------- prepack ----------------
// packed slab row r (0..127): ng=r>>5, gate=(r>>3)&3, jl=r&7
//   -> W_hh[gate*H + jb*32 + ng*8 + jl , k]  (warp ng holds all 4 gates for its 8 jj)
__global__ void prepack_kernel(const float* __restrict__ x,
                               const float* __restrict__ W_hh,
                               const float* __restrict__ b_out,
                               float* __restrict__ out)
{
    long i = (long)blockIdx.x * blockDim.x + threadIdx.x;
    long stride = (long)gridDim.x * blockDim.x;
    for (long idx = i; idx < (long)32 * 128 * Hh; idx += stride) {
        int k  = (int)(idx & (Hh - 1));
        int r  = (int)((idx >> 10) & 127);
        int jb = (int)(idx >> 17);
        int ng = r >> 5, g = (r >> 3) & 3, jl = r & 7;
        g_wp[idx] = __float2half(W_hh[(long)(g * Hh + jb * 32 + ng * 8 + jl) * Hh + k]);
    }
    for (long idx = i; idx < (long)Tt * Bb; idx += stride) {
        int b = (int)(idx & (Bb - 1));
        int t = (int)(idx >> 9);
        g_xT[idx] = x[(long)b * Tt + t];
    }
    for (long idx = i; idx < (long)2 * Bb * Hh; idx += stride)
        g_h[idx] = __float2half(0.0f);
    float bo = b_out[0];
    for (long idx = i; idx < (long)Bb * Tt; idx += stride)
        out[idx] = bo;
    if (i < 256) g_f[i] = 0;
}

// ---------------- persistent LSTM kernel: 2 warp-groups, chunk-granular
//                  cross-step wavefront (no global rendezvous) ----------------
__global__ void __launch_bounds__(NTHREADS, 1) lstm_main(
    const float* __restrict__ W_ih, const float* __restrict__ b_ih,
    const float* __restrict__ b_hh, const float* __restrict__ W_out,
    float* __restrict__ out)
{
    extern __shared__ char smem_raw[];
    uint32_t sraw = smem_u32(smem_raw);
    uint32_t s0 = (sraw + 1023u) & ~1023u;
    char* sm0 = smem_raw + (s0 - sraw);

    const int tid  = threadIdx.x;
    const int l    = tid & 31;
    const int w    = tid >> 5;
    const int g    = w >> 3;          // warp-group (batch half)
    const int lw   = w & 7;           // warp within group
    const int ltid = tid & 255;
    const int cta = blockIdx.x;
    const int mb = cta >> 5, jb = cta & 31;
    const int row0 = mb * 128, j0 = jb * 32;
    const int barid = 1 + g;
    const int c0 = ((jb >> 1) + g * 8) & 15;   // K-rotation: own pair first; halves offset
    const int* flg = g_f + (mb * 2 + g) * 32;  // this half's producer flags
    int* myflag = g_f + (mb * 2 + g) * 32 + jb;

    float* bias_s = (float*)(sm0);           // [128] gate*32 + jj
    float* wih_s  = (float*)(sm0 + 512);     // [128]
    float* wout_s = (float*)(sm0 + 1024);    // [32]
    const uint32_t GTILE = s0 + 2048 + (uint32_t)g * GRP_BYTES;  // this group's stages

    if (tid < 128) {
        int gg = tid >> 5, jj = tid & 31;
        int grow = gg * Hh + j0 + jj;
        bias_s[tid] = b_ih[grow] + b_hh[grow];
        wih_s[tid]  = W_ih[grow];
    }
    if (tid < 32) wout_s[tid] = W_out[j0 + tid];
    __syncthreads();

    // warp tiling within group: lw -> M-half (lw&1), ng = lw>>1 (32 gate-cols)
    const int M0 = (lw & 1) * 32;
    const int ng = lw >> 1;
    const int N0 = ng * 32;
    const int arow0 = M0 + (l & 7) + 8 * ((l >> 3) & 1);   // +16*mi
    const int agrn0 = (l >> 4);                             // + 2*kk
    const int brow0 = N0 + (l & 7) + 8 * (l >> 4);          // +16*p
    const int bgrn0 = (l >> 3) & 1;                         // + 2*kk
    const int l4 = l >> 2, l2 = (l & 3) * 2;
    const int jA = ng * 8 + l2;

    const char* baseB = (const char*)g_wp + (size_t)jb * 128 * (Hh * 2);

    float c[8];   // [mi*4 + rh*2 + e]
#pragma unroll
    for (int m = 0; m < 8; m++) c[m] = 0.0f;

#pragma unroll 1
    for (int t = 0; t < Tt; t++) {
        // h(t) read-buffer (t&1), h(t+1) write-buffer ((t+1)&1)
        const char* baseA = (const char*)g_h
            + ((size_t)(t & 1) * (Bb * Hh) + (size_t)(row0 + g * 64) * Hh) * 2;
        char* baseW = (char*)g_h
            + ((size_t)((t + 1) & 1) * (Bb * Hh) + 0) * 2;

        // ---- B prefetch chunks c0..c0+2 (h-independent, no gating) ----
#pragma unroll
        for (int s = 0; s < 3; s++) {
            int cc = (c0 + s) & 15;
            uint32_t tb = GTILE + s * STAGE_BYTES + 8192;
#pragma unroll
            for (int j = 0; j < 4; j++) {
                int q = ltid + 256 * j;
                int r = q >> 3, cb = q & 7;
                size_t go = (size_t)r * (Hh * 2) + (size_t)cc * (KCH * 2) + (size_t)cb * 16;
                cp16(tb + swz(r, cb), baseB + go);
            }
            cp_commit();
        }
        // ---- x values into registers ----
        float xvr[4];
#pragma unroll
        for (int mi = 0; mi < 2; mi++)
#pragma unroll
            for (int rh = 0; rh < 2; rh++)
                xvr[mi * 2 + rh] = g_xT[t * Bb + row0 + g * 64 + M0 + mi * 16 + rh * 8 + l4];
        // ---- warp0 gates the 3 prologue chunks' producer pairs ----
        if (lw == 0) {
#pragma unroll
            for (int s = 0; s < 3; s++) {
                int cc = (c0 + s) & 15;
                uint64_t f = ld_flags(flg + 2 * cc);
                while (!flags_ok(f, t)) f = ld_flags(flg + 2 * cc);
            }
        }
        bar_named(barid);   // release: warp0 acquired, bar propagates visibility to group
        // ---- A prefetch chunks c0..c0+2 ----
#pragma unroll
        for (int s = 0; s < 3; s++) {
            int cc = (c0 + s) & 15;
            uint32_t tb = GTILE + s * STAGE_BYTES;
#pragma unroll
            for (int j = 0; j < 2; j++) {
                int q = ltid + 256 * j;
                int r = q >> 3, cb = q & 7;
                size_t go = (size_t)r * (Hh * 2) + (size_t)cc * (KCH * 2) + (size_t)cb * 16;
                cp16(tb + swz(r, cb), baseA + go);
            }
            cp_commit();
        }
        // preload flag pair for chunk index 3 (hidden behind first chunk's MMAs)
        uint64_t f3 = 0;
        if (lw == 0) f3 = ld_flags(flg + 2 * ((c0 + 3) & 15));

        float acc[2][4][4];
#pragma unroll
        for (int mi = 0; mi < 2; mi++)
#pragma unroll
            for (int ni = 0; ni < 4; ni++)
#pragma unroll
                for (int e = 0; e < 4; e++) acc[mi][ni][e] = 0.0f;

        // ---- main K loop: 16 chunks of 64, rotated start, flag-gated prefetch ----
#pragma unroll 1
        for (int ch = 0; ch < NCHUNK; ch++) {
            int nci = ch + 3;
            // warp0: ensure producers of chunk nci published h(t) (flag prefetched)
            if (nci < NCHUNK && lw == 0) {
                int ncc = (c0 + nci) & 15;
                while (!flags_ok(f3, t)) f3 = ld_flags(flg + 2 * ncc);
            }
            if (ch < NCHUNK - 3) cp_wait2(); else cp_wait0();
            bar_named(barid);   // group warps done reading stage (ch+3)&3; poll visible

            if (nci < NCHUNK) {
                int ncc = (c0 + nci) & 15;
                uint32_t tb = GTILE + (nci & 3) * STAGE_BYTES;
#pragma unroll
                for (int j = 0; j < 2; j++) {
                    int q = ltid + 256 * j;
                    int r = q >> 3, cb = q & 7;
                    size_t go = (size_t)r * (Hh * 2) + (size_t)ncc * (KCH * 2) + (size_t)cb * 16;
                    cp16(tb + swz(r, cb), baseA + go);
                }
#pragma unroll
                for (int j = 0; j < 4; j++) {
                    int q = ltid + 256 * j;
                    int r = q >> 3, cb = q & 7;
                    size_t go = (size_t)r * (Hh * 2) + (size_t)ncc * (KCH * 2) + (size_t)cb * 16;
                    cp16(tb + 8192 + swz(r, cb), baseB + go);
                }
                cp_commit();
            }
            // prefetch next iteration's flag pair (latency hidden by MMAs below)
            if (nci + 1 < NCHUNK && lw == 0)
                f3 = ld_flags(flg + 2 * ((c0 + nci + 1) & 15));

            uint32_t As = GTILE + (ch & 3) * STAGE_BYTES;
            uint32_t Bs = As + 8192;

            uint32_t a[2][2][4];   // [buf][mi][4]
            uint32_t bf[2][4][2];  // [buf][ni][2]
#pragma unroll
            for (int mi = 0; mi < 2; mi++) {
                int r2 = arow0 + 16 * mi;
                ldsm_x4(a[0][mi], As + swz(r2, agrn0));
            }
#pragma unroll
            for (int p = 0; p < 2; p++) {
                uint32_t b4[4];
                int r2 = brow0 + 16 * p;
                ldsm_x4(b4, Bs + swz(r2, bgrn0));
                bf[0][2 * p][0] = b4[0]; bf[0][2 * p][1] = b4[1];
                bf[0][2 * p + 1][0] = b4[2]; bf[0][2 * p + 1][1] = b4[3];
            }
#pragma unroll
            for (int kk = 0; kk < 4; kk++) {
                int cur = kk & 1, nxt = cur ^ 1;
                if (kk < 3) {
                    int gr_a = 2 * (kk + 1) + agrn0;
                    int gr_b = 2 * (kk + 1) + bgrn0;
#pragma unroll
                    for (int mi = 0; mi < 2; mi++) {
                        int r2 = arow0 + 16 * mi;
                        ldsm_x4(a[nxt][mi], As + swz(r2, gr_a));
                    }
#pragma unroll
                    for (int p = 0; p < 2; p++) {
                        uint32_t b4[4];
                        int r2 = brow0 + 16 * p;
                        ldsm_x4(b4, Bs + swz(r2, gr_b));
                        bf[nxt][2 * p][0] = b4[0]; bf[nxt][2 * p][1] = b4[1];
                        bf[nxt][2 * p + 1][0] = b4[2]; bf[nxt][2 * p + 1][1] = b4[3];
                    }
                }
#pragma unroll
                for (int mi = 0; mi < 2; mi++)
#pragma unroll
                    for (int ni = 0; ni < 4; ni++)
                        mma16816(acc[mi][ni], a[cur][mi], bf[cur][ni][0], bf[cur][ni][1]);
            }
        }
        bar_named(barid);   // stages quiesced before next-iteration prefetch

        // ---- in-register LSTM combine; h(t+1) -> write buffer ----
#pragma unroll
        for (int mi = 0; mi < 2; mi++) {
#pragma unroll
            for (int rh = 0; rh < 2; rh++) {
                int rl = M0 + mi * 16 + rh * 8 + l4;
                float xv = xvr[mi * 2 + rh];
                float hv2[2];
                float hsum = 0.0f;
#pragma unroll
                for (int e = 0; e < 2; e++) {
                    int idx = rh * 2 + e;
                    int jj = jA + e;
                    float gi = acc[mi][0][idx] + xv * wih_s[jj]      + bias_s[jj];
                    float gf = acc[mi][1][idx] + xv * wih_s[32 + jj] + bias_s[32 + jj];
                    float gg = acc[mi][2][idx] + xv * wih_s[64 + jj] + bias_s[64 + jj];
                    float go = acc[mi][3][idx] + xv * wih_s[96 + jj] + bias_s[96 + jj];
                    int cm = mi * 4 + rh * 2 + e;
                    float cn = sigm(gf) * c[cm] + sigm(gi) * tanh_(gg);
                    c[cm] = cn;
                    float hv = sigm(go) * tanh_(cn);
                    hv2[e] = hv;
                    hsum += hv * wout_s[jj];
                }
                int growr = row0 + g * 64 + rl;
                *(__half2*)(baseW + ((size_t)growr * Hh + j0 + jA) * 2)
                    = __floats2half2_rn(hv2[0], hv2[1]);
                hsum += __shfl_xor_sync(0xffffffffu, hsum, 1);
                hsum += __shfl_xor_sync(0xffffffffu, hsum, 2);
                if ((l & 3) == 0)
                    atomicAdd(&out[(size_t)growr * Tt + t], hsum);
            }
        }
        // ---- publish this half's h(t+1): group rendezvous, one release-store ----
        bar_named(barid);
        if (ltid == 0) st_flag_release(myflag, t + 1);
    }
}

extern "C" void kernel_launch(void* const* d_in, const int* in_sizes, int n_in,
                              void* d_out, int out_size) {
    const float* x     = (const float*)d_in[0];
    const float* W_ih  = (const float*)d_in[1];
    const float* W_hh  = (const float*)d_in[2];
    const float* b_ih  = (const float*)d_in[3];
    const float* b_hh  = (const float*)d_in[4];
    const float* W_out = (const float*)d_in[5];
    const float* b_out = (const float*)d_in[6];
    float* out = (float*)d_out;

    cudaFuncSetAttribute(lstm_main, cudaFuncAttributeMaxDynamicSharedMemorySize, SMEM_DYN);

    prepack_kernel<<<2048, 256>>>(x, W_hh, b_out, out);
    lstm_main<<<NCTA, NTHREADS, SMEM_DYN>>>(W_ih, b_ih, b_hh, W_out, out);
}

// round 13
// speedup vs baseline: 1.5372x; 1.5372x over previous
#include <cuda_runtime.h>
#include <cuda_fp16.h>
#include <cstdint>

#define Bb 512
#define Tt 256
#define Hh 1024
#define NCTA 128
#define KCH 64
#define NCHUNK 16          // 1024 / 64
#define NSTG 4
#define STAGE_BYTES 24576  // A tile 8KB + B tile 16KB
#define GRP_BYTES (NSTG * STAGE_BYTES)   // 98304 per group
#define NTHREADS 512
#define SMEM_DYN (2048 + 2 * GRP_BYTES + 1024)

// persistent device state (static allocation — no cudaMalloc)
__device__ __half g_h[Bb * Hh];            // hidden state, fp16 [512,1024]
__device__ __half g_wp[32 * 128 * Hh];     // packed W_hh slabs, fp16 (gate-interleaved)
__device__ float  g_xT[Tt * Bb];           // x transposed [T,B]
__device__ int    g_bar8[8];               // [mb][half] barrier counters

// ---------------- helpers ----------------
__device__ __forceinline__ uint32_t smem_u32(const void* p) {
    uint32_t a;
    asm("{ .reg .u64 t; cvta.to.shared.u64 t, %1; cvt.u32.u64 %0, t; }" : "=r"(a) : "l"(p));
    return a;
}
__device__ __forceinline__ void cp16(uint32_t dst, const void* src) {
    unsigned long long g = __cvta_generic_to_global(src);
    asm volatile("cp.async.cg.shared.global [%0], [%1], 16;" :: "r"(dst), "l"(g) : "memory");
}
__device__ __forceinline__ void cp_commit() {
    asm volatile("cp.async.commit_group;" ::: "memory");
}
__device__ __forceinline__ void cp_wait2() {
    asm volatile("cp.async.wait_group 2;" ::: "memory");
}
__device__ __forceinline__ void cp_wait0() {
    asm volatile("cp.async.wait_group 0;" ::: "memory");
}
__device__ __forceinline__ void bar_named(int id) {
    asm volatile("bar.sync %0, 256;" :: "r"(id) : "memory");
}
__device__ __forceinline__ void ldsm_x4(uint32_t (&r)[4], uint32_t addr) {
    asm volatile("ldmatrix.sync.aligned.m8n8.x4.shared.b16 {%0,%1,%2,%3}, [%4];"
        : "=r"(r[0]), "=r"(r[1]), "=r"(r[2]), "=r"(r[3]) : "r"(addr));
}
__device__ __forceinline__ void mma16816(float (&d)[4], const uint32_t (&a)[4],
                                         uint32_t b0, uint32_t b1) {
    asm volatile("mma.sync.aligned.m16n8k16.row.col.f32.f16.f16.f32 "
        "{%0,%1,%2,%3}, {%4,%5,%6,%7}, {%8,%9}, {%0,%1,%2,%3};"
        : "+f"(d[0]), "+f"(d[1]), "+f"(d[2]), "+f"(d[3])
        : "r"(a[0]), "r"(a[1]), "r"(a[2]), "r"(a[3]), "r"(b0), "r"(b1));
}
// single-MUFU transcendentals: tanh.approx.f32 (sm_75+)
__device__ __forceinline__ float tanhap(float x) {
    float y; asm("tanh.approx.f32 %0, %1;" : "=f"(y) : "f"(x)); return y;
}
__device__ __forceinline__ float sigm(float x) { return fmaf(tanhap(0.5f * x), 0.5f, 0.5f); }
__device__ __forceinline__ float tanh_(float x) { return tanhap(x); }

__device__ __forceinline__ void bar_arrive_release(int* p) {
    asm volatile("red.release.gpu.global.add.u32 [%0], %1;" :: "l"(p), "r"(1) : "memory");
}
__device__ __forceinline__ int ld_acquire(const int* p) {
    int v;
    asm volatile("ld.acquire.gpu.global.u32 %0, [%1];" : "=r"(v) : "l"(p) : "memory");
    return v;
}

// swizzled byte offset within a 128B-row tile (granule = 16B, 8 per row)
__device__ __forceinline__ uint32_t swz(int r, int g) {
    return (uint32_t)(r * 128) + (uint32_t)(((g ^ (r & 7)) & 7) << 4);
}

// ---------------- prepack ----------------
// packed slab row r (0..127): ng=r>>5, gate=(r>>3)&3, jl=r&7
//   -> W_hh[gate*H + jb*32 + ng*8 + jl , k]  (warp ng holds all 4 gates for its 8 jj)
__global__ void prepack_kernel(const float* __restrict__ x,
                               const float* __restrict__ W_hh,
                               const float* __restrict__ b_out,
                               float* __restrict__ out)
{
    long i = (long)blockIdx.x * blockDim.x + threadIdx.x;
    long stride = (long)gridDim.x * blockDim.x;
    for (long idx = i; idx < (long)32 * 128 * Hh; idx += stride) {
        int k  = (int)(idx & (Hh - 1));
        int r  = (int)((idx >> 10) & 127);
        int jb = (int)(idx >> 17);
        int ng = r >> 5, g = (r >> 3) & 3, jl = r & 7;
        g_wp[idx] = __float2half(W_hh[(long)(g * Hh + jb * 32 + ng * 8 + jl) * Hh + k]);
    }
    for (long idx = i; idx < (long)Tt * Bb; idx += stride) {
        int b = (int)(idx & (Bb - 1));
        int t = (int)(idx >> 9);
        g_xT[idx] = x[(long)b * Tt + t];
    }
    for (long idx = i; idx < (long)Bb * Hh; idx += stride)
        g_h[idx] = __float2half(0.0f);
    float bo = b_out[0];
    for (long idx = i; idx < (long)Bb * Tt; idx += stride)
        out[idx] = bo;
    if (i < 8) g_bar8[i] = 0;
}

// ---------------- persistent LSTM kernel: 2 independent warp-groups ----------------
__global__ void __launch_bounds__(NTHREADS, 1) lstm_main(
    const float* __restrict__ W_ih, const float* __restrict__ b_ih,
    const float* __restrict__ b_hh, const float* __restrict__ W_out,
    float* __restrict__ out)
{
    extern __shared__ char smem_raw[];
    uint32_t sraw = smem_u32(smem_raw);
    uint32_t s0 = (sraw + 1023u) & ~1023u;
    char* sm0 = smem_raw + (s0 - sraw);

    const int tid  = threadIdx.x;
    const int l    = tid & 31;
    const int w    = tid >> 5;
    const int g    = w >> 3;          // warp-group (batch half)
    const int lw   = w & 7;           // warp within group
    const int ltid = tid & 255;
    const int cta = blockIdx.x;
    const int mb = cta >> 5, jb = cta & 31;
    const int row0 = mb * 128, j0 = jb * 32;
    int* mybar = g_bar8 + mb * 2 + g;
    const int barid = 1 + g;

    float* bias_s = (float*)(sm0);           // [128] gate*32 + jj
    float* wih_s  = (float*)(sm0 + 512);     // [128]
    float* wout_s = (float*)(sm0 + 1024);    // [32]
    const uint32_t GTILE = s0 + 2048 + (uint32_t)g * GRP_BYTES;  // this group's stages

    if (tid < 128) {
        int gg = tid >> 5, jj = tid & 31;
        int grow = gg * Hh + j0 + jj;
        bias_s[tid] = b_ih[grow] + b_hh[grow];
        wih_s[tid]  = W_ih[grow];
    }
    if (tid < 32) wout_s[tid] = W_out[j0 + tid];
    __syncthreads();

    // warp tiling within group: lw -> M-half (lw&1), ng = lw>>1 (32 gate-cols)
    const int M0 = (lw & 1) * 32;
    const int ng = lw >> 1;
    const int N0 = ng * 32;
    const int arow0 = M0 + (l & 7) + 8 * ((l >> 3) & 1);   // +16*mi
    const int agrn0 = (l >> 4);                             // + 2*kk
    const int brow0 = N0 + (l & 7) + 8 * (l >> 4);          // +16*p
    const int bgrn0 = (l >> 3) & 1;                         // + 2*kk
    const int l4 = l >> 2, l2 = (l & 3) * 2;
    const int jA = ng * 8 + l2;

    const char* baseA = (const char*)g_h  + (size_t)(row0 + g * 64) * (Hh * 2);
    const char* baseB = (const char*)g_wp + (size_t)jb * 128 * (Hh * 2);

    float c[8];   // [mi*4 + rh*2 + e]
#pragma unroll
    for (int m = 0; m < 8; m++) c[m] = 0.0f;

    // anti-phase seed: delay half 1 so the two chains interleave mainloop/tail
    if (g == 1) {
        long long t0 = clock64();
        while (clock64() - t0 < 24000) { }
    }

    // ---- initial B prologue for step 0 (chunks 0..2) ----
#pragma unroll
    for (int s = 0; s < 3; s++) {
        uint32_t tb = GTILE + s * STAGE_BYTES + 8192;
#pragma unroll
        for (int j = 0; j < 4; j++) {
            int q = ltid + 256 * j;
            int r = q >> 3, cb = q & 7;
            size_t go = (size_t)r * (Hh * 2) + (size_t)s * (KCH * 2) + (size_t)cb * 16;
            cp16(tb + swz(r, cb), baseB + go);
        }
        cp_commit();
    }

#pragma unroll 1
    for (int t = 0; t < Tt; t++) {
        // ---- x values into registers (h-independent, hidden by the spin) ----
        float xvr[4];
#pragma unroll
        for (int mi = 0; mi < 2; mi++)
#pragma unroll
            for (int rh = 0; rh < 2; rh++)
                xvr[mi * 2 + rh] = g_xT[t * Bb + row0 + g * 64 + M0 + mi * 16 + rh * 8 + l4];
        // ---- spin: this half's h(t-1) published by all 32 CTAs of the mb-group ----
        if (ltid == 0) {
            int target = 32 * t;
            while (ld_acquire(mybar) < target) { }
        }
        bar_named(barid);
        // ---- A prefetch chunks 0..2 (B for these stages already in flight) ----
#pragma unroll
        for (int s = 0; s < 3; s++) {
            uint32_t tb = GTILE + s * STAGE_BYTES;
#pragma unroll
            for (int j = 0; j < 2; j++) {
                int q = ltid + 256 * j;
                int r = q >> 3, cb = q & 7;
                size_t go = (size_t)r * (Hh * 2) + (size_t)s * (KCH * 2) + (size_t)cb * 16;
                cp16(tb + swz(r, cb), baseA + go);
            }
            cp_commit();
        }

        float acc[2][4][4];
#pragma unroll
        for (int mi = 0; mi < 2; mi++)
#pragma unroll
            for (int ni = 0; ni < 4; ni++)
#pragma unroll
                for (int e = 0; e < 4; e++) acc[mi][ni][e] = 0.0f;

        // ---- main K loop: 16 chunks of 64, distance-3 prefetch, 4 stages ----
#pragma unroll 1
        for (int ch = 0; ch < NCHUNK; ch++) {
            if (ch < NCHUNK - 3) cp_wait2(); else cp_wait0();
            bar_named(barid);   // all group warps done reading stage (ch+3)&3 (chunk ch-1)

            int nc = ch + 3;
            if (nc < NCHUNK) {
                uint32_t tb = GTILE + (nc & 3) * STAGE_BYTES;
#pragma unroll
                for (int j = 0; j < 2; j++) {
                    int q = ltid + 256 * j;
                    int r = q >> 3, cb = q & 7;
                    size_t go = (size_t)r * (Hh * 2) + (size_t)nc * (KCH * 2) + (size_t)cb * 16;
                    cp16(tb + swz(r, cb), baseA + go);
                }
#pragma unroll
                for (int j = 0; j < 4; j++) {
                    int q = ltid + 256 * j;
                    int r = q >> 3, cb = q & 7;
                    size_t go = (size_t)r * (Hh * 2) + (size_t)nc * (KCH * 2) + (size_t)cb * 16;
                    cp16(tb + 8192 + swz(r, cb), baseB + go);
                }
                cp_commit();   // only real groups are committed (no empty groups)
            }

            uint32_t As = GTILE + (ch & 3) * STAGE_BYTES;
            uint32_t Bs = As + 8192;

            uint32_t a[2][2][4];   // [buf][mi][4]
            uint32_t bf[2][4][2];  // [buf][ni][2]
#pragma unroll
            for (int mi = 0; mi < 2; mi++) {
                int r2 = arow0 + 16 * mi;
                ldsm_x4(a[0][mi], As + swz(r2, agrn0));
            }
#pragma unroll
            for (int p = 0; p < 2; p++) {
                uint32_t b4[4];
                int r2 = brow0 + 16 * p;
                ldsm_x4(b4, Bs + swz(r2, bgrn0));
                bf[0][2 * p][0] = b4[0]; bf[0][2 * p][1] = b4[1];
                bf[0][2 * p + 1][0] = b4[2]; bf[0][2 * p + 1][1] = b4[3];
            }
#pragma unroll
            for (int kk = 0; kk < 4; kk++) {
                int cur = kk & 1, nxt = cur ^ 1;
                if (kk < 3) {
                    int gr_a = 2 * (kk + 1) + agrn0;
                    int gr_b = 2 * (kk + 1) + bgrn0;
#pragma unroll
                    for (int mi = 0; mi < 2; mi++) {
                        int r2 = arow0 + 16 * mi;
                        ldsm_x4(a[nxt][mi], As + swz(r2, gr_a));
                    }
#pragma unroll
                    for (int p = 0; p < 2; p++) {
                        uint32_t b4[4];
                        int r2 = brow0 + 16 * p;
                        ldsm_x4(b4, Bs + swz(r2, gr_b));
                        bf[nxt][2 * p][0] = b4[0]; bf[nxt][2 * p][1] = b4[1];
                        bf[nxt][2 * p + 1][0] = b4[2]; bf[nxt][2 * p + 1][1] = b4[3];
                    }
                }
#pragma unroll
                for (int mi = 0; mi < 2; mi++)
#pragma unroll
                    for (int ni = 0; ni < 4; ni++)
                        mma16816(acc[mi][ni], a[cur][mi], bf[cur][ni][0], bf[cur][ni][1]);
            }
        }
        bar_named(barid);   // stages quiesced

        // ---- B prefetch for NEXT step (overlaps the epilogue below) ----
        if (t + 1 < Tt) {
#pragma unroll
            for (int s = 0; s < 3; s++) {
                uint32_t tb = GTILE + s * STAGE_BYTES + 8192;
#pragma unroll
                for (int j = 0; j < 4; j++) {
                    int q = ltid + 256 * j;
                    int r = q >> 3, cb = q & 7;
                    size_t go = (size_t)r * (Hh * 2) + (size_t)s * (KCH * 2) + (size_t)cb * 16;
                    cp16(tb + swz(r, cb), baseB + go);
                }
                cp_commit();
            }
        }

        // ---- in-register LSTM combine: compute + h store; head-sum kept in regs ----
        float hsumr[4];
#pragma unroll
        for (int mi = 0; mi < 2; mi++) {
#pragma unroll
            for (int rh = 0; rh < 2; rh++) {
                int rl = M0 + mi * 16 + rh * 8 + l4;
                float xv = xvr[mi * 2 + rh];
                float hv2[2];
                float hsum = 0.0f;
#pragma unroll
                for (int e = 0; e < 2; e++) {
                    int idx = rh * 2 + e;
                    int jj = jA + e;
                    float gi = acc[mi][0][idx] + xv * wih_s[jj]      + bias_s[jj];
                    float gf = acc[mi][1][idx] + xv * wih_s[32 + jj] + bias_s[32 + jj];
                    float gg = acc[mi][2][idx] + xv * wih_s[64 + jj] + bias_s[64 + jj];
                    float go = acc[mi][3][idx] + xv * wih_s[96 + jj] + bias_s[96 + jj];
                    int cm = mi * 4 + rh * 2 + e;
                    float cn = sigm(gf) * c[cm] + sigm(gi) * tanh_(gg);
                    c[cm] = cn;
                    float hv = sigm(go) * tanh_(cn);
                    hv2[e] = hv;
                    hsum += hv * wout_s[jj];
                }
                int growr = row0 + g * 64 + rl;
                *(__half2*)((char*)g_h + ((size_t)growr * Hh + j0 + jA) * 2)
                    = __floats2half2_rn(hv2[0], hv2[1]);
                hsumr[mi * 2 + rh] = hsum;
            }
        }
        // ---- publish this half's h(t) FIRST (critical path), then head output ----
        bar_named(barid);
        if (ltid == 0) bar_arrive_release(mybar);
#pragma unroll
        for (int mi = 0; mi < 2; mi++) {
#pragma unroll
            for (int rh = 0; rh < 2; rh++) {
                float hs = hsumr[mi * 2 + rh];
                hs += __shfl_xor_sync(0xffffffffu, hs, 1);
                hs += __shfl_xor_sync(0xffffffffu, hs, 2);
                if ((l & 3) == 0) {
                    int rl = M0 + mi * 16 + rh * 8 + l4;
                    int growr = row0 + g * 64 + rl;
                    atomicAdd(&out[(size_t)growr * Tt + t], hs);
                }
            }
        }
    }
}

extern "C" void kernel_launch(void* const* d_in, const int* in_sizes, int n_in,
                              void* d_out, int out_size) {
    const float* x     = (const float*)d_in[0];
    const float* W_ih  = (const float*)d_in[1];
    const float* W_hh  = (const float*)d_in[2];
    const float* b_ih  = (const float*)d_in[3];
    const float* b_hh  = (const float*)d_in[4];
    const float* W_out = (const float*)d_in[5];
    const float* b_out = (const float*)d_in[6];
    float* out = (float*)d_out;

    cudaFuncSetAttribute(lstm_main, cudaFuncAttributeMaxDynamicSharedMemorySize, SMEM_DYN);

    prepack_kernel<<<2048, 256>>>(x, W_hh, b_out, out);
    lstm_main<<<NCTA, NTHREADS, SMEM_DYN>>>(W_ih, b_ih, b_hh, W_out, out);
}

// round 14
// speedup vs baseline: 1.5556x; 1.0119x over previous
#include <cuda_runtime.h>
#include <cuda_fp16.h>
#include <cstdint>

#define Bb 512
#define Tt 256
#define Hh 1024
#define NCTA 128
#define KCH 64
#define NCHUNK 16            // 1024 / 64
#define NSTG 3
#define ASTG_BYTES 16384     // A stage: 128 rows x 64 k-cols fp16
#define B_BYTES 131072       // resident B: 64 rows x 1024 cols fp16
#define NTHREADS 512
#define SMEM_DYN (256 + 1024 + B_BYTES + 2 * NSTG * ASTG_BYTES)   // 230656

// persistent device state (static allocation — no cudaMalloc)
__device__ __half g_h[2 * Bb * Hh];        // double-buffered hidden state, fp16
__device__ __half g_wp[64 * 64 * Hh];      // packed W_hh slabs: 64 jb x 64 rows x 1024
__device__ float  g_xT[Tt * Bb];           // x transposed [T,B]
__device__ int    g_bar4[4];               // [mb][half] barrier counters

// ---------------- helpers ----------------
__device__ __forceinline__ uint32_t smem_u32(const void* p) {
    uint32_t a;
    asm("{ .reg .u64 t; cvta.to.shared.u64 t, %1; cvt.u32.u64 %0, t; }" : "=r"(a) : "l"(p));
    return a;
}
__device__ __forceinline__ void cp16(uint32_t dst, const void* src) {
    unsigned long long g = __cvta_generic_to_global(src);
    asm volatile("cp.async.cg.shared.global [%0], [%1], 16;" :: "r"(dst), "l"(g) : "memory");
}
__device__ __forceinline__ void cp_commit() {
    asm volatile("cp.async.commit_group;" ::: "memory");
}
__device__ __forceinline__ void cp_wait1() {
    asm volatile("cp.async.wait_group 1;" ::: "memory");
}
__device__ __forceinline__ void cp_wait0() {
    asm volatile("cp.async.wait_group 0;" ::: "memory");
}
__device__ __forceinline__ void bar_named(int id) {
    asm volatile("bar.sync %0, 256;" :: "r"(id) : "memory");
}
__device__ __forceinline__ void ldsm_x4(uint32_t (&r)[4], uint32_t addr) {
    asm volatile("ldmatrix.sync.aligned.m8n8.x4.shared.b16 {%0,%1,%2,%3}, [%4];"
        : "=r"(r[0]), "=r"(r[1]), "=r"(r[2]), "=r"(r[3]) : "r"(addr));
}
__device__ __forceinline__ void mma16816(float (&d)[4], const uint32_t (&a)[4],
                                         uint32_t b0, uint32_t b1) {
    asm volatile("mma.sync.aligned.m16n8k16.row.col.f32.f16.f16.f32 "
        "{%0,%1,%2,%3}, {%4,%5,%6,%7}, {%8,%9}, {%0,%1,%2,%3};"
        : "+f"(d[0]), "+f"(d[1]), "+f"(d[2]), "+f"(d[3])
        : "r"(a[0]), "r"(a[1]), "r"(a[2]), "r"(a[3]), "r"(b0), "r"(b1));
}
// single-MUFU transcendentals
__device__ __forceinline__ float tanhap(float x) {
    float y; asm("tanh.approx.f32 %0, %1;" : "=f"(y) : "f"(x)); return y;
}
__device__ __forceinline__ float sigm(float x) { return fmaf(tanhap(0.5f * x), 0.5f, 0.5f); }
__device__ __forceinline__ float tanh_(float x) { return tanhap(x); }

__device__ __forceinline__ void bar_arrive_release(int* p) {
    asm volatile("red.release.gpu.global.add.u32 [%0], %1;" :: "l"(p), "r"(1) : "memory");
}
__device__ __forceinline__ int ld_acquire(const int* p) {
    int v;
    asm volatile("ld.acquire.gpu.global.u32 %0, [%1];" : "=r"(v) : "l"(p) : "memory");
    return v;
}

// swizzled byte offset within a 128B-row tile (granule = 16B, 8 per row)
__device__ __forceinline__ uint32_t swz(int r, int g) {
    return (uint32_t)(r * 128) + (uint32_t)(((g ^ (r & 7)) & 7) << 4);
}

// ---------------- prepack ----------------
// packed slab (jb 0..63) row r (0..63): ng=r>>5, gate=(r>>3)&3, jl=r&7
//   -> W_hh[gate*H + jb*16 + ng*8 + jl , k]
__global__ void prepack_kernel(const float* __restrict__ x,
                               const float* __restrict__ W_hh,
                               const float* __restrict__ b_out,
                               float* __restrict__ out)
{
    long i = (long)blockIdx.x * blockDim.x + threadIdx.x;
    long stride = (long)gridDim.x * blockDim.x;
    for (long idx = i; idx < (long)64 * 64 * Hh; idx += stride) {
        int k  = (int)(idx & (Hh - 1));
        int r  = (int)((idx >> 10) & 63);
        int jb = (int)(idx >> 16);
        int ng = r >> 5, g = (r >> 3) & 3, jl = r & 7;
        g_wp[idx] = __float2half(W_hh[(long)(g * Hh + jb * 16 + ng * 8 + jl) * Hh + k]);
    }
    for (long idx = i; idx < (long)Tt * Bb; idx += stride) {
        int b = (int)(idx & (Bb - 1));
        int t = (int)(idx >> 9);
        g_xT[idx] = x[(long)b * Tt + t];
    }
    for (long idx = i; idx < (long)2 * Bb * Hh; idx += stride)
        g_h[idx] = __float2half(0.0f);
    float bo = b_out[0];
    for (long idx = i; idx < (long)Bb * Tt; idx += stride)
        out[idx] = bo;
    if (i < 4) g_bar4[i] = 0;
}

// ---------------- persistent LSTM kernel: resident-B, 2 independent M-groups ----------------
__global__ void __launch_bounds__(NTHREADS, 1) lstm_main(
    const float* __restrict__ W_ih, const float* __restrict__ b_ih,
    const float* __restrict__ b_hh, const float* __restrict__ W_out,
    float* __restrict__ out)
{
    extern __shared__ char smem_raw[];
    uint32_t sraw = smem_u32(smem_raw);
    uint32_t s0 = (sraw + 127u) & ~127u;
    char* sm0 = smem_raw + (s0 - sraw);

    const int tid  = threadIdx.x;
    const int l    = tid & 31;
    const int w    = tid >> 5;
    const int g    = w >> 3;          // warp-group (128-row half of this CTA's 256 rows)
    const int lw   = w & 7;           // warp within group
    const int ltid = tid & 255;
    const int cta = blockIdx.x;
    const int mb = cta >> 6, jb = cta & 63;
    const int row0 = mb * 256, j0 = jb * 16;
    int* mybar = g_bar4 + mb * 2 + g;
    const int barid = 1 + g;

    float* bias_s = (float*)(sm0);           // [64]  gate*16 + jj_local
    float* wih_s  = (float*)(sm0 + 256);     // [64]
    float* wout_s = (float*)(sm0 + 512);     // [16]
    const uint32_t BOFF  = s0 + 1024;                      // resident B, 16 chunk-tiles x 8KB
    const uint32_t GTILE = s0 + 1024 + B_BYTES + (uint32_t)g * (NSTG * ASTG_BYTES);

    if (tid < 64) {
        int gate = tid >> 4, jl = tid & 15;
        int grow = gate * Hh + j0 + jl;
        bias_s[tid] = b_ih[grow] + b_hh[grow];
        wih_s[tid]  = W_ih[grow];
    }
    if (tid < 16) wout_s[tid] = W_out[j0 + tid];

    // ---- one-time resident B load (all 512 threads cooperate) ----
    {
        const char* baseB = (const char*)g_wp + (size_t)jb * 64 * (Hh * 2);
#pragma unroll
        for (int j = 0; j < 16; j++) {
            int q = tid + 512 * j;           // 0..8191 granules of 16B
            int chn = q >> 9;                // chunk tile (512 granules each)
            int qi = q & 511;
            int r = qi >> 3, cb = qi & 7;
            cp16(BOFF + chn * 8192 + swz(r, cb),
                 baseB + (size_t)r * (Hh * 2) + (size_t)chn * (KCH * 2) + (size_t)cb * 16);
        }
        cp_commit();
        cp_wait0();
        __syncthreads();
    }

    // warp tiling within group: M0 = (lw&3)*32 over 128 rows, ng = lw>>2 over 64 N-cols
    const int M0 = (lw & 3) * 32;
    const int ng = lw >> 2;
    const int N0 = ng * 32;
    const int arow0 = M0 + (l & 7) + 8 * ((l >> 3) & 1);   // +16*mi
    const int agrn0 = (l >> 4);                             // + 2*kk
    const int brow0 = N0 + (l & 7) + 8 * (l >> 4);          // +16*p
    const int bgrn0 = (l >> 3) & 1;                         // + 2*kk
    const int l4 = l >> 2, l2 = (l & 3) * 2;
    const int jA = ng * 8 + l2;                             // jj_local for e=0 (0..15)

    float c[8];   // [mi*4 + rh*2 + e]
#pragma unroll
    for (int m = 0; m < 8; m++) c[m] = 0.0f;

    // anti-phase seed: delay half 1 so the two chains interleave mainloop/tail
    if (g == 1) {
        long long t0 = clock64();
        while (clock64() - t0 < 24000) { }
    }

#pragma unroll 1
    for (int t = 0; t < Tt; t++) {
        const char* baseA = (const char*)g_h
            + ((size_t)(t & 1) * (Bb * Hh) + (size_t)(row0 + g * 128) * Hh) * 2;
        char* baseW = (char*)g_h + ((size_t)((t + 1) & 1) * (Bb * Hh)) * 2;

        // ---- x values into registers (h-independent, hidden by the spin) ----
        float xvr[4];
#pragma unroll
        for (int mi = 0; mi < 2; mi++)
#pragma unroll
            for (int rh = 0; rh < 2; rh++)
                xvr[mi * 2 + rh] = g_xT[t * Bb + row0 + g * 128 + M0 + mi * 16 + rh * 8 + l4];
        // ---- spin: this half's h(t-1) published by all 64 CTAs of the mb-group ----
        if (ltid == 0) {
            int target = 64 * t;
            while (ld_acquire(mybar) < target) { }
        }
        bar_named(barid);
        // ---- A prologue: chunks 0,1 ----
#pragma unroll
        for (int s = 0; s < 2; s++) {
            uint32_t tb = GTILE + s * ASTG_BYTES;
#pragma unroll
            for (int j = 0; j < 4; j++) {
                int q = ltid + 256 * j;      // 0..1023 granules
                int r = q >> 3, cb = q & 7;  // r 0..127
                size_t go = (size_t)r * (Hh * 2) + (size_t)s * (KCH * 2) + (size_t)cb * 16;
                cp16(tb + swz(r, cb), baseA + go);
            }
            cp_commit();
        }

        float acc[2][4][4];
#pragma unroll
        for (int mi = 0; mi < 2; mi++)
#pragma unroll
            for (int ni = 0; ni < 4; ni++)
#pragma unroll
                for (int e = 0; e < 4; e++) acc[mi][ni][e] = 0.0f;

        // ---- main K loop: 16 chunks of 64; A streamed (dist-2, 3 stages), B resident ----
#pragma unroll 1
        for (int ch = 0; ch < NCHUNK; ch++) {
            if (ch < NCHUNK - 2) cp_wait1(); else cp_wait0();
            bar_named(barid);   // all group warps done with stage (ch+2)%3 (chunk ch-1)

            int nc = ch + 2;
            if (nc < NCHUNK) {
                uint32_t tb = GTILE + (nc % NSTG) * ASTG_BYTES;
#pragma unroll
                for (int j = 0; j < 4; j++) {
                    int q = ltid + 256 * j;
                    int r = q >> 3, cb = q & 7;
                    size_t go = (size_t)r * (Hh * 2) + (size_t)nc * (KCH * 2) + (size_t)cb * 16;
                    cp16(tb + swz(r, cb), baseA + go);
                }
                cp_commit();   // only real groups committed
            }

            uint32_t As = GTILE + (ch % NSTG) * ASTG_BYTES;
            uint32_t Bs = BOFF + ch * 8192;

            uint32_t a[2][2][4];   // [buf][mi][4]
            uint32_t bf[2][4][2];  // [buf][ni][2]
#pragma unroll
            for (int mi = 0; mi < 2; mi++) {
                int r2 = arow0 + 16 * mi;
                ldsm_x4(a[0][mi], As + swz(r2, agrn0));
            }
#pragma unroll
            for (int p = 0; p < 2; p++) {
                uint32_t b4[4];
                int r2 = brow0 + 16 * p;
                ldsm_x4(b4, Bs + swz(r2, bgrn0));
                bf[0][2 * p][0] = b4[0]; bf[0][2 * p][1] = b4[1];
                bf[0][2 * p + 1][0] = b4[2]; bf[0][2 * p + 1][1] = b4[3];
            }
#pragma unroll
            for (int kk = 0; kk < 4; kk++) {
                int cur = kk & 1, nxt = cur ^ 1;
                if (kk < 3) {
                    int gr_a = 2 * (kk + 1) + agrn0;
                    int gr_b = 2 * (kk + 1) + bgrn0;
#pragma unroll
                    for (int mi = 0; mi < 2; mi++) {
                        int r2 = arow0 + 16 * mi;
                        ldsm_x4(a[nxt][mi], As + swz(r2, gr_a));
                    }
#pragma unroll
                    for (int p = 0; p < 2; p++) {
                        uint32_t b4[4];
                        int r2 = brow0 + 16 * p;
                        ldsm_x4(b4, Bs + swz(r2, gr_b));
                        bf[nxt][2 * p][0] = b4[0]; bf[nxt][2 * p][1] = b4[1];
                        bf[nxt][2 * p + 1][0] = b4[2]; bf[nxt][2 * p + 1][1] = b4[3];
                    }
                }
#pragma unroll
                for (int mi = 0; mi < 2; mi++)
#pragma unroll
                    for (int ni = 0; ni < 4; ni++)
                        mma16816(acc[mi][ni], a[cur][mi], bf[cur][ni][0], bf[cur][ni][1]);
            }
        }
        bar_named(barid);   // stages quiesced before next-iteration prologue

        // ---- in-register LSTM combine: compute + h store; head-sum kept in regs ----
        float hsumr[4];
#pragma unroll
        for (int mi = 0; mi < 2; mi++) {
#pragma unroll
            for (int rh = 0; rh < 2; rh++) {
                int rl = M0 + mi * 16 + rh * 8 + l4;
                float xv = xvr[mi * 2 + rh];
                float hv2[2];
                float hsum = 0.0f;
#pragma unroll
                for (int e = 0; e < 2; e++) {
                    int idx = rh * 2 + e;
                    int jj = jA + e;   // 0..15 within CTA's 16 hidden cols
                    float gi = acc[mi][0][idx] + xv * wih_s[jj]      + bias_s[jj];
                    float gf = acc[mi][1][idx] + xv * wih_s[16 + jj] + bias_s[16 + jj];
                    float gg = acc[mi][2][idx] + xv * wih_s[32 + jj] + bias_s[32 + jj];
                    float go = acc[mi][3][idx] + xv * wih_s[48 + jj] + bias_s[48 + jj];
                    int cm = mi * 4 + rh * 2 + e;
                    float cn = sigm(gf) * c[cm] + sigm(gi) * tanh_(gg);
                    c[cm] = cn;
                    float hv = sigm(go) * tanh_(cn);
                    hv2[e] = hv;
                    hsum += hv * wout_s[jj];
                }
                int growr = row0 + g * 128 + rl;
                *(__half2*)(baseW + ((size_t)growr * Hh + j0 + jA) * 2)
                    = __floats2half2_rn(hv2[0], hv2[1]);
                hsumr[mi * 2 + rh] = hsum;
            }
        }
        // ---- publish this half's h(t+1) FIRST, then head output ----
        bar_named(barid);
        if (ltid == 0) bar_arrive_release(mybar);
#pragma unroll
        for (int mi = 0; mi < 2; mi++) {
#pragma unroll
            for (int rh = 0; rh < 2; rh++) {
                float hs = hsumr[mi * 2 + rh];
                hs += __shfl_xor_sync(0xffffffffu, hs, 1);
                hs += __shfl_xor_sync(0xffffffffu, hs, 2);
                if ((l & 3) == 0) {
                    int rl = M0 + mi * 16 + rh * 8 + l4;
                    int growr = row0 + g * 128 + rl;
                    atomicAdd(&out[(size_t)growr * Tt + t], hs);
                }
            }
        }
    }
}

extern "C" void kernel_launch(void* const* d_in, const int* in_sizes, int n_in,
                              void* d_out, int out_size) {
    const float* x     = (const float*)d_in[0];
    const float* W_ih  = (const float*)d_in[1];
    const float* W_hh  = (const float*)d_in[2];
    const float* b_ih  = (const float*)d_in[3];
    const float* b_hh  = (const float*)d_in[4];
    const float* W_out = (const float*)d_in[5];
    const float* b_out = (const float*)d_in[6];
    float* out = (float*)d_out;

    cudaFuncSetAttribute(lstm_main, cudaFuncAttributeMaxDynamicSharedMemorySize, SMEM_DYN);

    prepack_kernel<<<2048, 256>>>(x, W_hh, b_out, out);
    lstm_main<<<NCTA, NTHREADS, SMEM_DYN>>>(W_ih, b_ih, b_hh, W_out, out);
}